// round 4
// baseline (speedup 1.0000x reference)
#include <cuda_runtime.h>
#include <cstdint>

// Problem constants (match reference)
#define NV   100000
#define NE   20000
#define DD   64
#define ALPHA 0.5f
#define BETA  0.5f

#define NBKT   (NE + NV)      // [0,NE) edge buckets, [NE,NE+NV) vertex buckets
#define MAXNNZ 1000000

#define GRID_A 148
#define TPB_A  1024

// ---------------------------------------------------------------------------
// Scratch (__device__ globals only; no allocation)
// ---------------------------------------------------------------------------
__device__ __align__(16) float g_Xe[NE * DD];
__device__ int g_counts[NBKT];
__device__ int g_offs[NBKT];
__device__ int g_cur[NBKT];
__device__ int g_bsum[GRID_A];
__device__ int g_perm[2 * MAXNNZ];

__device__ unsigned g_bar_count = 0;
__device__ volatile unsigned g_bar_gen = 0;

// ---------------------------------------------------------------------------
// Software grid barrier (requires all GRID_A blocks co-resident: 1 block/SM)
// ---------------------------------------------------------------------------
__device__ __forceinline__ void grid_bar() {
    __syncthreads();
    if (threadIdx.x == 0) {
        __threadfence();
        unsigned gen = g_bar_gen;
        if (atomicAdd(&g_bar_count, 1u) == gridDim.x - 1) {
            g_bar_count = 0;
            __threadfence();
            g_bar_gen = gen + 1;
        } else {
            while (g_bar_gen == gen) { __nanosleep(64); }
        }
        __threadfence();
    }
    __syncthreads();
}

// ---------------------------------------------------------------------------
// Block-wide exclusive scan over 1024 threads (shuffle + smem partials)
// ---------------------------------------------------------------------------
__device__ __forceinline__ int block_exscan_1024(int v, int& block_total) {
    __shared__ int wsum[32];
    int lane = threadIdx.x & 31;
    int wid  = threadIdx.x >> 5;
    int inc = v;
    #pragma unroll
    for (int d = 1; d < 32; d <<= 1) {
        int t = __shfl_up_sync(0xFFFFFFFFu, inc, d);
        if (lane >= d) inc += t;
    }
    if (lane == 31) wsum[wid] = inc;
    __syncthreads();
    if (wid == 0) {
        int s = wsum[lane];
        #pragma unroll
        for (int d = 1; d < 32; d <<= 1) {
            int t = __shfl_up_sync(0xFFFFFFFFu, s, d);
            if (lane >= d) s += t;
        }
        wsum[lane] = s;
    }
    __syncthreads();
    int woff = (wid > 0) ? wsum[wid - 1] : 0;
    block_total = wsum[31];
    int r = woff + inc - v;
    __syncthreads();   // wsum reused across calls
    return r;
}

// ---------------------------------------------------------------------------
// Shared gather helper: sum rows of src listed in bucket b (global bucket id)
// 16 threads/bucket, this thread owns floats [c, c+4)
// ---------------------------------------------------------------------------
__device__ __forceinline__ void f4acc(float4& a, float4 x) {
    a.x += x.x; a.y += x.y; a.z += x.z; a.w += x.w;
}

__device__ __forceinline__ float4 gather_bucket(const float* __restrict__ src,
                                                int bkt, int c) {
    int start = __ldg(g_offs + bkt);
    int deg   = __ldg(g_counts + bkt);
    float4 a0 = make_float4(0.f, 0.f, 0.f, 0.f);
    float4 a1 = a0, a2 = a0, a3 = a0;
    int j = 0;
    for (; j + 4 <= deg; j += 4) {
        int i0 = __ldg(g_perm + start + j);
        int i1 = __ldg(g_perm + start + j + 1);
        int i2 = __ldg(g_perm + start + j + 2);
        int i3 = __ldg(g_perm + start + j + 3);
        f4acc(a0, *reinterpret_cast<const float4*>(src + (size_t)i0 * DD + c));
        f4acc(a1, *reinterpret_cast<const float4*>(src + (size_t)i1 * DD + c));
        f4acc(a2, *reinterpret_cast<const float4*>(src + (size_t)i2 * DD + c));
        f4acc(a3, *reinterpret_cast<const float4*>(src + (size_t)i3 * DD + c));
    }
    for (; j < deg; ++j) {
        int i0 = __ldg(g_perm + start + j);
        f4acc(a0, *reinterpret_cast<const float4*>(src + (size_t)i0 * DD + c));
    }
    float4 r;
    r.x = (a0.x + a1.x) + (a2.x + a3.x);
    r.y = (a0.y + a1.y) + (a2.y + a3.y);
    r.z = (a0.z + a1.z) + (a2.z + a3.z);
    r.w = (a0.w + a1.w) + (a2.w + a3.w);
    return r;
}

// ---------------------------------------------------------------------------
// Kernel A (persistent): zero -> histogram -> scan -> fill -> gather_e
// ---------------------------------------------------------------------------
__global__ __launch_bounds__(TPB_A, 1) void build_and_gather_e(
        const float* __restrict__ X,
        const int* __restrict__ vertex,
        const int* __restrict__ edges,
        int nnz) {
    const int T    = gridDim.x * TPB_A;
    const int gtid = blockIdx.x * TPB_A + threadIdx.x;

    // --- zero counts ---
    for (int i = gtid; i < NBKT; i += T) g_counts[i] = 0;
    grid_bar();

    // --- histogram ---
    for (int i = gtid; i < nnz; i += T) {
        atomicAdd(&g_counts[__ldg(edges + i)], 1);
        atomicAdd(&g_counts[NE + __ldg(vertex + i)], 1);
    }
    grid_bar();

    // --- scan phase 1: each block scans its 1024-chunk ---
    {
        int i = blockIdx.x * TPB_A + threadIdx.x;
        int v = (i < NBKT) ? g_counts[i] : 0;
        int total;
        int ex = block_exscan_1024(v, total);
        if (i < NBKT) g_offs[i] = ex;
        if (threadIdx.x == 0) g_bsum[blockIdx.x] = total;
    }
    grid_bar();

    // --- scan phase 2: block 0 exclusive-scans block sums ---
    if (blockIdx.x == 0) {
        int v = (threadIdx.x < GRID_A) ? g_bsum[threadIdx.x] : 0;
        int total;
        int ex = block_exscan_1024(v, total);
        if (threadIdx.x < GRID_A) g_bsum[threadIdx.x] = ex;
    }
    grid_bar();

    // --- scan phase 3: add block offsets; init cursors ---
    for (int i = gtid; i < NBKT; i += T) {
        int o = g_offs[i] + g_bsum[i >> 10];
        g_offs[i] = o;
        g_cur[i]  = o;
    }
    grid_bar();

    // --- fill perm (bucket sort) ---
    for (int i = gtid; i < nnz; i += T) {
        int e = __ldg(edges + i);
        int v = __ldg(vertex + i);
        g_perm[atomicAdd(&g_cur[e], 1)] = v;
        g_perm[atomicAdd(&g_cur[NE + v], 1)] = e;
    }
    grid_bar();

    // --- gather_e: Xe[e] = sum_{v in bucket e} X[v] ---
    for (int t = gtid; t < NE * 16; t += T) {
        int b = t >> 4;
        int c = (t & 15) << 2;
        float4 r = gather_bucket(X, b, c);
        *reinterpret_cast<float4*>(g_Xe + (size_t)b * DD + c) = r;
    }
}

// ---------------------------------------------------------------------------
// f32x2 packed-FMA helpers (Blackwell)
// ---------------------------------------------------------------------------
__device__ __forceinline__ uint64_t pack2(float lo, float hi) {
    uint64_t r;
    asm("mov.b64 %0, {%1, %2};" : "=l"(r) : "f"(lo), "f"(hi));
    return r;
}
__device__ __forceinline__ void ffma2(uint64_t& d, uint64_t a, uint64_t b) {
    asm("fma.rn.f32x2 %0, %1, %2, %3;" : "=l"(d) : "l"(a), "l"(b), "l"(d));
}
__device__ __forceinline__ float2 unpack2(uint64_t v) {
    float lo, hi;
    asm("mov.b64 {%0, %1}, %2;" : "=f"(lo), "=f"(hi) : "l"(v));
    return make_float2(lo, hi);
}

// ---------------------------------------------------------------------------
// Kernel B: fused gather_v + MLP epilogue.
// One block = 64 rows, 256 threads, thread computes a 4x4 output block.
// Xi / h kept TRANSPOSED in smem: ST[k*PAD + row] so A-operand loads are LDS.128.
// ---------------------------------------------------------------------------
#define PAD 68

__global__ __launch_bounds__(256) void epilogue_fused(
        const float* __restrict__ X0,
        const float* __restrict__ W1, const float* __restrict__ b1,
        const float* __restrict__ W2, const float* __restrict__ b2,
        float* __restrict__ out) {
    __shared__ float ST[64 * PAD];   // [k][row], transposed activations
    __shared__ float Ws[64 * 64];    // W1 then W2, row-major [k][n]
    __shared__ float bs[64];

    const int tid  = threadIdx.x;
    const int tr   = tid >> 4;
    const int tc   = tid & 15;
    const int r0   = tr * 4;
    const int c0   = tc * 4;
    const int base = blockIdx.x * 64;

    // Load W1 + b1
    #pragma unroll
    for (int idx = tid; idx < 64 * 16; idx += 256)
        reinterpret_cast<float4*>(Ws)[idx] = reinterpret_cast<const float4*>(W1)[idx];
    if (tid < 64) bs[tid] = b1[tid];

    // Gather Xv for this tile's rows and build Xi = 0.5*Xv + 0.5*X0 (transposed)
    {
        int grp = tid >> 4;          // row-within-pass
        int cg  = (tid & 15) << 2;   // float offset within row
        #pragma unroll
        for (int p = 0; p < 4; ++p) {
            int r   = p * 16 + grp;
            int row = base + r;
            float4 xi = make_float4(0.f, 0.f, 0.f, 0.f);
            if (row < NV) {
                float4 gv = gather_bucket(g_Xe, NE + row, cg);
                float4 x0 = *reinterpret_cast<const float4*>(X0 + (size_t)row * DD + cg);
                xi.x = (1.f - ALPHA) * gv.x + ALPHA * x0.x;
                xi.y = (1.f - ALPHA) * gv.y + ALPHA * x0.y;
                xi.z = (1.f - ALPHA) * gv.z + ALPHA * x0.z;
                xi.w = (1.f - ALPHA) * gv.w + ALPHA * x0.w;
            }
            ST[(cg + 0) * PAD + r] = xi.x;
            ST[(cg + 1) * PAD + r] = xi.y;
            ST[(cg + 2) * PAD + r] = xi.z;
            ST[(cg + 3) * PAD + r] = xi.w;
        }
    }
    __syncthreads();

    // GEMM 1: acc = Xi @ W1   (packed f32x2: acc[i][0]=(c0,c0+1) acc[i][1]=(c0+2,c0+3))
    uint64_t acc[4][2];
    #pragma unroll
    for (int i = 0; i < 4; ++i) { acc[i][0] = 0ull; acc[i][1] = 0ull; }
    #pragma unroll 16
    for (int k = 0; k < 64; ++k) {
        float4 av = *reinterpret_cast<const float4*>(ST + k * PAD + r0);
        float4 bv = *reinterpret_cast<const float4*>(Ws + k * 64 + c0);
        uint64_t b01 = pack2(bv.x, bv.y);
        uint64_t b23 = pack2(bv.z, bv.w);
        uint64_t a0 = pack2(av.x, av.x);
        uint64_t a1 = pack2(av.y, av.y);
        uint64_t a2 = pack2(av.z, av.z);
        uint64_t a3 = pack2(av.w, av.w);
        ffma2(acc[0][0], a0, b01); ffma2(acc[0][1], a0, b23);
        ffma2(acc[1][0], a1, b01); ffma2(acc[1][1], a1, b23);
        ffma2(acc[2][0], a2, b01); ffma2(acc[2][1], a2, b23);
        ffma2(acc[3][0], a3, b01); ffma2(acc[3][1], a3, b23);
    }

    // Stash Xi 4x4 (column vectors: xi[j] = Xi[r0..r0+3][c0+j])
    float4 xi[4];
    #pragma unroll
    for (int j = 0; j < 4; ++j)
        xi[j] = *reinterpret_cast<const float4*>(ST + (c0 + j) * PAD + r0);
    __syncthreads();   // all reads of ST done

    // h = relu(acc + b1) -> ST (transposed); load W2
    #pragma unroll
    for (int i = 0; i < 4; ++i) {
        float2 p01 = unpack2(acc[i][0]);
        float2 p23 = unpack2(acc[i][1]);
        ST[(c0 + 0) * PAD + r0 + i] = fmaxf(p01.x + bs[c0 + 0], 0.f);
        ST[(c0 + 1) * PAD + r0 + i] = fmaxf(p01.y + bs[c0 + 1], 0.f);
        ST[(c0 + 2) * PAD + r0 + i] = fmaxf(p23.x + bs[c0 + 2], 0.f);
        ST[(c0 + 3) * PAD + r0 + i] = fmaxf(p23.y + bs[c0 + 3], 0.f);
    }
    #pragma unroll
    for (int idx = tid; idx < 64 * 16; idx += 256)
        reinterpret_cast<float4*>(Ws)[idx] = reinterpret_cast<const float4*>(W2)[idx];
    __syncthreads();

    float b2r[4];
    #pragma unroll
    for (int j = 0; j < 4; ++j) b2r[j] = __ldg(b2 + c0 + j);

    // GEMM 2: acc = h @ W2
    #pragma unroll
    for (int i = 0; i < 4; ++i) { acc[i][0] = 0ull; acc[i][1] = 0ull; }
    #pragma unroll 16
    for (int k = 0; k < 64; ++k) {
        float4 av = *reinterpret_cast<const float4*>(ST + k * PAD + r0);
        float4 bv = *reinterpret_cast<const float4*>(Ws + k * 64 + c0);
        uint64_t b01 = pack2(bv.x, bv.y);
        uint64_t b23 = pack2(bv.z, bv.w);
        uint64_t a0 = pack2(av.x, av.x);
        uint64_t a1 = pack2(av.y, av.y);
        uint64_t a2 = pack2(av.z, av.z);
        uint64_t a3 = pack2(av.w, av.w);
        ffma2(acc[0][0], a0, b01); ffma2(acc[0][1], a0, b23);
        ffma2(acc[1][0], a1, b01); ffma2(acc[1][1], a1, b23);
        ffma2(acc[2][0], a2, b01); ffma2(acc[2][1], a2, b23);
        ffma2(acc[3][0], a3, b01); ffma2(acc[3][1], a3, b23);
    }

    // out = (1-BETA)*Xi + BETA*(acc + b2)
    #pragma unroll
    for (int i = 0; i < 4; ++i) {
        int row = base + r0 + i;
        if (row < NV) {
            float2 p01 = unpack2(acc[i][0]);
            float2 p23 = unpack2(acc[i][1]);
            float4 o;
            o.x = (1.f - BETA) * (&xi[0].x)[i] + BETA * (p01.x + b2r[0]);
            o.y = (1.f - BETA) * (&xi[1].x)[i] + BETA * (p01.y + b2r[1]);
            o.z = (1.f - BETA) * (&xi[2].x)[i] + BETA * (p23.x + b2r[2]);
            o.w = (1.f - BETA) * (&xi[3].x)[i] + BETA * (p23.y + b2r[3]);
            *reinterpret_cast<float4*>(out + (size_t)row * DD + c0) = o;
        }
    }
}

// ---------------------------------------------------------------------------
extern "C" void kernel_launch(void* const* d_in, const int* in_sizes, int n_in,
                              void* d_out, int out_size) {
    const float* X      = (const float*)d_in[0];
    const float* X0     = (const float*)d_in[1];
    const float* W1     = (const float*)d_in[2];
    const float* b1     = (const float*)d_in[3];
    const float* W2     = (const float*)d_in[4];
    const float* b2     = (const float*)d_in[5];
    const int*   vertex = (const int*)d_in[6];
    const int*   edges  = (const int*)d_in[7];
    float*       out    = (float*)d_out;

    const int nnz = in_sizes[6];

    build_and_gather_e<<<GRID_A, TPB_A>>>(X, vertex, edges, nnz);
    epilogue_fused<<<(NV + 63) / 64, 256>>>(X0, W1, b1, W2, b2, out);
}